// round 1
// baseline (speedup 1.0000x reference)
#include <cuda_runtime.h>

// ---------------------------------------------------------------------------
// NARX-NN restructured: the D=4 scan with h0=0 collapses into per-absolute-time
// quantities:
//   V[s]  = relu(x[s]@W_in + b_in) @ W_xh + b_h
//   H1[s] = tanh(V[s])                       G1 = H1 @ W_hh
//   H2[s] = tanh(V[s] + G1[s-1])             G2 = H2 @ W_hh
//   H3[s] = tanh(V[s] + G2[s-1])             G3 = H3 @ W_hh
//   out[t]= tanh(V[t-1] + G3[t-2]) @ W_out + b_out   (t in [4, 512))
// Zero-padding G[s-1] at s=0 only affects H/G values never consumed by a
// valid output (out[t] needs V[t-4..t-1] only, all with s>=0 lookbacks).
//
// All GEMMs are [1.05M x 64] @ [64 x 64] fp32, implemented with packed
// fma.rn.f32x2 (2 FMA/instr) — per-thread 4-row x 8-col tiles, H duplicated
// (h,h) in shared for free splats, W as native float2 pairs.
// ---------------------------------------------------------------------------

#define NTT   512
#define NGRID 2048
#define NX    16
#define HID   64
#define NROWS (NTT * NGRID)   // 1,048,576

typedef unsigned long long ull;

// Scratch (device globals are the sanctioned allocation-free workaround)
__device__ float g_V [(size_t)NROWS * HID];
__device__ float g_Ga[(size_t)NROWS * HID];
__device__ float g_Gb[(size_t)NROWS * HID];

// ---- f32x2 packed math helpers --------------------------------------------
__device__ __forceinline__ ull pk2(float a, float b) {
    ull r; asm("mov.b64 %0, {%1,%2};" : "=l"(r) : "f"(a), "f"(b)); return r;
}
__device__ __forceinline__ ull fma2(ull a, ull b, ull c) {
    ull d; asm("fma.rn.f32x2 %0, %1, %2, %3;" : "=l"(d) : "l"(a), "l"(b), "l"(c));
    return d;
}
__device__ __forceinline__ float2 up2(ull v) {
    float2 f; asm("mov.b64 {%0,%1}, %2;" : "=f"(f.x), "=f"(f.y) : "l"(v)); return f;
}
// Fast accurate tanh: 1 - 2/(e^{2x}+1). ex2/rcp approx => ~1e-6 abs error.
// Saturates correctly at +/-1 for large |x| (exp -> inf / 0).
__device__ __forceinline__ float ftanh(float x) {
    float e = __expf(2.0f * x);
    return 1.0f - __fdividef(2.0f, e + 1.0f);
}

// ---- shared 64x64 GEMM micro-kernel (phase 2) ------------------------------
// Hd: [64][128] duplicated-(h,h) 8B entries, k-major.  Ws: [64][64] row-major.
// Thread tile: rows r0..r0+3, cols {c0..c0+3} U {32+c0..32+c0+3}.
__device__ __forceinline__ void gemm_phase2(const ull* __restrict__ Hd,
                                            const float* __restrict__ Ws,
                                            ull acc[4][4], int r0, int c0) {
#pragma unroll
    for (int k = 0; k < 64; k++) {
        const ulonglong2 wA = *(const ulonglong2*)(Ws + k * 64 + c0);
        const ulonglong2 wB = *(const ulonglong2*)(Ws + k * 64 + 32 + c0);
        const ulonglong2 hA = *(const ulonglong2*)(Hd + k * 128 + r0);
        const ulonglong2 hB = *(const ulonglong2*)(Hd + k * 128 + r0 + 2);
        acc[0][0] = fma2(hA.x, wA.x, acc[0][0]);
        acc[0][1] = fma2(hA.x, wA.y, acc[0][1]);
        acc[0][2] = fma2(hA.x, wB.x, acc[0][2]);
        acc[0][3] = fma2(hA.x, wB.y, acc[0][3]);
        acc[1][0] = fma2(hA.y, wA.x, acc[1][0]);
        acc[1][1] = fma2(hA.y, wA.y, acc[1][1]);
        acc[1][2] = fma2(hA.y, wB.x, acc[1][2]);
        acc[1][3] = fma2(hA.y, wB.y, acc[1][3]);
        acc[2][0] = fma2(hB.x, wA.x, acc[2][0]);
        acc[2][1] = fma2(hB.x, wA.y, acc[2][1]);
        acc[2][2] = fma2(hB.x, wB.x, acc[2][2]);
        acc[2][3] = fma2(hB.x, wB.y, acc[2][3]);
        acc[3][0] = fma2(hB.y, wA.x, acc[3][0]);
        acc[3][1] = fma2(hB.y, wA.y, acc[3][1]);
        acc[3][2] = fma2(hB.y, wB.x, acc[3][2]);
        acc[3][3] = fma2(hB.y, wB.y, acc[3][3]);
    }
}

__device__ __forceinline__ void store_tile(float* __restrict__ Gout,
                                           const ull acc[4][4],
                                           size_t rbase, int r0, int c0) {
#pragma unroll
    for (int r = 0; r < 4; r++) {
        const size_t row = rbase + r0 + r;
        *(ulonglong2*)(Gout + row * 64 + c0)      = make_ulonglong2(acc[r][0], acc[r][1]);
        *(ulonglong2*)(Gout + row * 64 + 32 + c0) = make_ulonglong2(acc[r][2], acc[r][3]);
    }
}

// ---- Stage A: V = relu(x@W_in + b_in) @ W_xh + b_h -------------------------
#define SMEM_A (64 * 128 * 8 + (4096 + 1024 + 64 + 64) * 4)

__global__ __launch_bounds__(256, 2)
void stageA_kernel(const float* __restrict__ x, const float* __restrict__ Win,
                   const float* __restrict__ bin, const float* __restrict__ Wxh,
                   const float* __restrict__ bh, float* __restrict__ Vout) {
    extern __shared__ char smraw[];
    ull*   Ud  = (ull*)smraw;                 // [64][128] dup u
    float* Ws  = (float*)(Ud + 64 * 128);     // W_xh 64x64
    float* Wi  = Ws + 4096;                   // W_in 16x64
    float* bi  = Wi + 1024;                   // b_in 64
    float* bhs = bi + 64;                     // b_h  64
    const int tid = threadIdx.x;
    const size_t rbase = (size_t)blockIdx.x * 128;

    {   // weights -> shared
        const float4* s1 = (const float4*)Wxh; float4* d1 = (float4*)Ws;
#pragma unroll
        for (int i = 0; i < 4; i++) d1[tid + i * 256] = s1[tid + i * 256];
        ((float4*)Wi)[tid & 255] = ((const float4*)Win)[tid & 255];
        if (tid < 16)                 ((float4*)bi)[tid]       = ((const float4*)bin)[tid];
        else if (tid < 32)            ((float4*)bhs)[tid - 16] = ((const float4*)bh)[tid - 16];
    }
    __syncthreads();

    {   // phase A1: u = relu(x@W_in + b_in), stored duplicated & k-major
        const int rl = tid >> 1;
        const int j0 = (tid & 1) * 32;
        const size_t row = rbase + rl;
        float xr[16];
        const float4* xp = (const float4*)(x + row * NX);
#pragma unroll
        for (int q = 0; q < 4; q++) {
            float4 t = xp[q];
            xr[q * 4] = t.x; xr[q * 4 + 1] = t.y; xr[q * 4 + 2] = t.z; xr[q * 4 + 3] = t.w;
        }
        ull ua[16];
        const ull* bip = (const ull*)bi;
#pragma unroll
        for (int jj = 0; jj < 16; jj++) ua[jj] = bip[(j0 >> 1) + jj];
#pragma unroll
        for (int k = 0; k < 16; k++) {
            const ull xs = pk2(xr[k], xr[k]);
            const ulonglong2* wp = (const ulonglong2*)(Wi + k * 64 + j0);
#pragma unroll
            for (int j2 = 0; j2 < 8; j2++) {
                ulonglong2 w = wp[j2];
                ua[j2 * 2]     = fma2(xs, w.x, ua[j2 * 2]);
                ua[j2 * 2 + 1] = fma2(xs, w.y, ua[j2 * 2 + 1]);
            }
        }
#pragma unroll
        for (int jj = 0; jj < 16; jj++) {
            float2 f = up2(ua[jj]);
            float u0 = fmaxf(f.x, 0.0f), u1 = fmaxf(f.y, 0.0f);
            Ud[(j0 + jj * 2)     * 128 + rl] = pk2(u0, u0);
            Ud[(j0 + jj * 2 + 1) * 128 + rl] = pk2(u1, u1);
        }
    }
    __syncthreads();

    // phase A2: V = u @ W_xh + b_h
    const int cg = tid & 7, rg = tid >> 3;
    const int r0 = rg * 4, c0 = cg * 4;
    ull acc[4][4];
    {
        const ull* bhp = (const ull*)bhs;
        const ull b0 = bhp[cg * 2], b1 = bhp[cg * 2 + 1];
        const ull b2 = bhp[16 + cg * 2], b3 = bhp[16 + cg * 2 + 1];
#pragma unroll
        for (int r = 0; r < 4; r++) { acc[r][0] = b0; acc[r][1] = b1; acc[r][2] = b2; acc[r][3] = b3; }
    }
    gemm_phase2(Ud, Ws, acc, r0, c0);
    store_tile(Vout, acc, rbase, r0, c0);
}

// ---- Step kernel: Gout = tanh(Vin + shift(Gin)) @ W_hh ---------------------
#define SMEM_STEP (64 * 128 * 8 + 4096 * 4)

template <bool HASG>
__global__ __launch_bounds__(256, 2)
void step_kernel(const float* __restrict__ Vin, const float* __restrict__ Gin,
                 const float* __restrict__ Whh, float* __restrict__ Gout) {
    extern __shared__ char smraw[];
    ull*   Hd = (ull*)smraw;               // [64][128] dup tanh(v+g)
    float* Ws = (float*)(Hd + 64 * 128);   // W_hh 64x64
    const int tid = threadIdx.x;
    const size_t rbase = (size_t)blockIdx.x * 128;

    {   // W_hh -> shared
        const float4* src = (const float4*)Whh; float4* dst = (float4*)Ws;
#pragma unroll
        for (int i = 0; i < 4; i++) dst[tid + i * 256] = src[tid + i * 256];
    }
    {   // phase 1: H = tanh(V + G[s-1])
        const int rl = tid >> 1;
        const int j0 = (tid & 1) * 32;
        const size_t row = rbase + rl;
        const float4* vp = (const float4*)(Vin + row * 64 + j0);
        const bool hg = HASG && (row >= (size_t)NGRID);
        const float4* gp = (const float4*)(Gin + (row - NGRID) * 64 + j0);
#pragma unroll
        for (int q = 0; q < 8; q++) {
            float4 v = vp[q];
            if (hg) { float4 g = gp[q]; v.x += g.x; v.y += g.y; v.z += g.z; v.w += g.w; }
            float t0 = ftanh(v.x), t1 = ftanh(v.y), t2 = ftanh(v.z), t3 = ftanh(v.w);
            const int j = j0 + q * 4;
            Hd[(j + 0) * 128 + rl] = pk2(t0, t0);
            Hd[(j + 1) * 128 + rl] = pk2(t1, t1);
            Hd[(j + 2) * 128 + rl] = pk2(t2, t2);
            Hd[(j + 3) * 128 + rl] = pk2(t3, t3);
        }
    }
    __syncthreads();

    const int cg = tid & 7, rg = tid >> 3;
    const int r0 = rg * 4, c0 = cg * 4;
    ull acc[4][4];
#pragma unroll
    for (int r = 0; r < 4; r++)
#pragma unroll
        for (int p = 0; p < 4; p++) acc[r][p] = 0ULL;   // (0.f, 0.f)
    gemm_phase2(Hd, Ws, acc, r0, c0);
    store_tile(Gout, acc, rbase, r0, c0);
}

// ---- Stage E: out[t] = tanh(V[t-1] + G3[t-2]) @ W_out + b_out --------------
__global__ __launch_bounds__(256)
void stageE_kernel(const float* __restrict__ Vin, const float* __restrict__ G3,
                   const float* __restrict__ Wout, const float* __restrict__ bout,
                   float* __restrict__ out) {
    __shared__ float wo[64];
    if (threadIdx.x < 16) ((float4*)wo)[threadIdx.x] = ((const float4*)Wout)[threadIdx.x];
    __syncthreads();
    const size_t idx = (size_t)blockIdx.x * 256 + threadIdx.x;
    const size_t row = idx + (size_t)3 * NGRID;        // s in [3, 511)
    const float4* vp = (const float4*)(Vin + row * 64);
    const float4* gp = (const float4*)(G3 + (row - NGRID) * 64);
    float y = bout[0];
#pragma unroll
    for (int q = 0; q < 16; q++) {
        float4 v = vp[q], g = gp[q];
        y += ftanh(v.x + g.x) * wo[q * 4]     + ftanh(v.y + g.y) * wo[q * 4 + 1]
           + ftanh(v.z + g.z) * wo[q * 4 + 2] + ftanh(v.w + g.w) * wo[q * 4 + 3];
    }
    out[row + NGRID] = y;   // t = s + 1
}

__global__ void zero_head(float* __restrict__ out) {
    out[(size_t)blockIdx.x * 1024 + threadIdx.x] = 0.0f;   // t in [0,4)
}

// ---------------------------------------------------------------------------
extern "C" void kernel_launch(void* const* d_in, const int* in_sizes, int n_in,
                              void* d_out, int out_size) {
    const float* x    = (const float*)d_in[0];
    const float* Win  = (const float*)d_in[1];
    const float* bin  = (const float*)d_in[2];
    const float* Wxh  = (const float*)d_in[3];
    const float* Whh  = (const float*)d_in[4];
    const float* bh   = (const float*)d_in[5];
    const float* Wout = (const float*)d_in[6];
    const float* bout = (const float*)d_in[7];
    float* out = (float*)d_out;

    float *V, *Ga, *Gb;
    cudaGetSymbolAddress((void**)&V,  g_V);
    cudaGetSymbolAddress((void**)&Ga, g_Ga);
    cudaGetSymbolAddress((void**)&Gb, g_Gb);

    cudaFuncSetAttribute(stageA_kernel, cudaFuncAttributeMaxDynamicSharedMemorySize, SMEM_A);
    cudaFuncSetAttribute(step_kernel<false>, cudaFuncAttributeMaxDynamicSharedMemorySize, SMEM_STEP);
    cudaFuncSetAttribute(step_kernel<true>,  cudaFuncAttributeMaxDynamicSharedMemorySize, SMEM_STEP);

    const int NB = NROWS / 128;   // 8192 blocks

    zero_head<<<8, 1024>>>(out);
    stageA_kernel<<<NB, 256, SMEM_A>>>(x, Win, bin, Wxh, bh, V);
    step_kernel<false><<<NB, 256, SMEM_STEP>>>(V, V,  Whh, Ga);   // G1
    step_kernel<true ><<<NB, 256, SMEM_STEP>>>(V, Ga, Whh, Gb);   // G2
    step_kernel<true ><<<NB, 256, SMEM_STEP>>>(V, Gb, Whh, Ga);   // G3
    stageE_kernel<<<(508 * NGRID) / 256, 256>>>(V, Ga, Wout, bout, out);
}

// round 3
// speedup vs baseline: 1.2934x; 1.2934x over previous
#include <cuda_runtime.h>

// ---------------------------------------------------------------------------
// NARX-NN restructured:
//   V[s]  = relu(x[s]@W_in + b_in) @ W_xh + b_h
//   G1[s] = tanh(V[s]) @ W_hh
//   G2[s] = tanh(V[s] + G1[s-1]) @ W_hh
//   G3[s] = tanh(V[s] + G2[s-1]) @ W_hh
//   out[t]= tanh(V[t-1] + G3[t-2]) @ W_out + b_out,  t in [4, 512)
//
// Intermediates stored TRANSPOSED [HID][NROWS]: coalesced STG.128 of the
// row-pair-packed f32x2 accumulators, coalesced LDG for phase-1 readers.
//
// GEMM core: rows packed into f32x2 pairs, W columns DUPLICATED in shared.
// W reads are warp-uniform -> broadcast (1 wavefront/LDS.128); H reads serve
// 4 rows per LDS.128. 4x16 thread tile => FMA-issue-bound, not crossbar-bound.
// ---------------------------------------------------------------------------

#define NTT   512
#define NGRID 2048
#define NX    16
#define HID   64
#define NROWS (NTT * NGRID)   // 1,048,576

typedef unsigned long long ull;

__device__ float g_V [(size_t)HID * NROWS];
__device__ float g_Ga[(size_t)HID * NROWS];
__device__ float g_Gb[(size_t)HID * NROWS];

// ---- f32x2 helpers ---------------------------------------------------------
__device__ __forceinline__ ull pk2(float a, float b) {
    ull r; asm("mov.b64 %0, {%1,%2};" : "=l"(r) : "f"(a), "f"(b)); return r;
}
__device__ __forceinline__ ull fma2(ull a, ull b, ull c) {
    ull d; asm("fma.rn.f32x2 %0, %1, %2, %3;" : "=l"(d) : "l"(a), "l"(b), "l"(c));
    return d;
}
__device__ __forceinline__ float2 up2(ull v) {
    float2 f; asm("mov.b64 {%0,%1}, %2;" : "=f"(f.x), "=f"(f.y) : "l"(v)); return f;
}
// tanh(x) = 1 - 2/(e^{2x}+1); ~1e-6 abs err, saturates correctly.
__device__ __forceinline__ float ftanh(float x) {
    float e = __expf(2.0f * x);
    return 1.0f - __fdividef(2.0f, e + 1.0f);
}

// ---- 256-row x 64-col GEMM core -------------------------------------------
// Hs: [64][256] plain floats, k-major.  Wd: [64][128] duplicated columns.
// Thread tile: 4 rows (2 f32x2 pairs) x 16 cols. Warp: 128 rows x 16 cols.
__device__ __forceinline__ void gemm64(const float* __restrict__ Hs,
                                       const float* __restrict__ Wd,
                                       ull acc[2][16], int roff, int c0) {
#pragma unroll 16
    for (int k = 0; k < 64; k++) {
        const ulonglong2 h = *(const ulonglong2*)(Hs + (k << 8) + roff);
        const ulonglong2* wp = (const ulonglong2*)(Wd + (k << 7) + (c0 << 1));
        const ulonglong2 w0 = wp[0], w1 = wp[1], w2 = wp[2], w3 = wp[3];
        const ulonglong2 w4 = wp[4], w5 = wp[5], w6 = wp[6], w7 = wp[7];
        acc[0][ 0] = fma2(h.x, w0.x, acc[0][ 0]); acc[1][ 0] = fma2(h.y, w0.x, acc[1][ 0]);
        acc[0][ 1] = fma2(h.x, w0.y, acc[0][ 1]); acc[1][ 1] = fma2(h.y, w0.y, acc[1][ 1]);
        acc[0][ 2] = fma2(h.x, w1.x, acc[0][ 2]); acc[1][ 2] = fma2(h.y, w1.x, acc[1][ 2]);
        acc[0][ 3] = fma2(h.x, w1.y, acc[0][ 3]); acc[1][ 3] = fma2(h.y, w1.y, acc[1][ 3]);
        acc[0][ 4] = fma2(h.x, w2.x, acc[0][ 4]); acc[1][ 4] = fma2(h.y, w2.x, acc[1][ 4]);
        acc[0][ 5] = fma2(h.x, w2.y, acc[0][ 5]); acc[1][ 5] = fma2(h.y, w2.y, acc[1][ 5]);
        acc[0][ 6] = fma2(h.x, w3.x, acc[0][ 6]); acc[1][ 6] = fma2(h.y, w3.x, acc[1][ 6]);
        acc[0][ 7] = fma2(h.x, w3.y, acc[0][ 7]); acc[1][ 7] = fma2(h.y, w3.y, acc[1][ 7]);
        acc[0][ 8] = fma2(h.x, w4.x, acc[0][ 8]); acc[1][ 8] = fma2(h.y, w4.x, acc[1][ 8]);
        acc[0][ 9] = fma2(h.x, w4.y, acc[0][ 9]); acc[1][ 9] = fma2(h.y, w4.y, acc[1][ 9]);
        acc[0][10] = fma2(h.x, w5.x, acc[0][10]); acc[1][10] = fma2(h.y, w5.x, acc[1][10]);
        acc[0][11] = fma2(h.x, w5.y, acc[0][11]); acc[1][11] = fma2(h.y, w5.y, acc[1][11]);
        acc[0][12] = fma2(h.x, w6.x, acc[0][12]); acc[1][12] = fma2(h.y, w6.x, acc[1][12]);
        acc[0][13] = fma2(h.x, w6.y, acc[0][13]); acc[1][13] = fma2(h.y, w6.y, acc[1][13]);
        acc[0][14] = fma2(h.x, w7.x, acc[0][14]); acc[1][14] = fma2(h.y, w7.x, acc[1][14]);
        acc[0][15] = fma2(h.x, w7.y, acc[0][15]); acc[1][15] = fma2(h.y, w7.y, acc[1][15]);
    }
}

__device__ __forceinline__ void store_t(float* __restrict__ out, const ull acc[2][16],
                                        size_t rbase, int roff, int c0) {
#pragma unroll
    for (int c = 0; c < 16; c++) {
        *(ulonglong2*)(out + (size_t)(c0 + c) * NROWS + rbase + roff) =
            make_ulonglong2(acc[0][c], acc[1][c]);
    }
}

#define SMEM_STEP (64 * 256 * 4 + 64 * 128 * 4)                 // 98304
#define SMEM_A    (SMEM_STEP + 16 * 64 * 4 + 64 * 4 + 128 * 4)  // 103168

// ---- Step kernel: Got = tanh(Vt + shift(Gt)) @ W_hh ------------------------
template <bool HASG>
__global__ __launch_bounds__(256, 2)
void step_kernel(const float* __restrict__ Vt, const float* __restrict__ Gt,
                 const float* __restrict__ Whh, float* __restrict__ Got) {
    extern __shared__ float sm[];
    float* Hs = sm;               // [64][256]
    float* Wd = sm + 64 * 256;    // [64][128] dup
    const int tid = threadIdx.x;
    const size_t rbase = (size_t)blockIdx.x * 256;

#pragma unroll
    for (int i = tid; i < 4096; i += 256) {
        const float w = Whh[i];
        Wd[2 * i] = w; Wd[2 * i + 1] = w;    // 2i = k*128 + 2c for i = k*64+c
    }
    {   // phase 1: H = tanh(V + G[s-1]), k-major into shared (coalesced LDG).
        // Full unroll-by-16 batches the strided loads -> high MLP.
        const size_t row = rbase + tid;
        const bool hg = HASG && (rbase >= (size_t)NGRID);   // uniform per block
        const float* vp = Vt + row;
        const float* gp = Gt + row - NGRID;
#pragma unroll
        for (int kb = 0; kb < 4; kb++) {
            float v[16];
#pragma unroll
            for (int j = 0; j < 16; j++) v[j] = vp[(size_t)(kb * 16 + j) * NROWS];
            if (hg) {
#pragma unroll
                for (int j = 0; j < 16; j++) v[j] += gp[(size_t)(kb * 16 + j) * NROWS];
            }
#pragma unroll
            for (int j = 0; j < 16; j++)
                Hs[((kb * 16 + j) << 8) + tid] = ftanh(v[j]);
        }
    }
    __syncthreads();

    const int w = tid >> 5, lane = tid & 31;
    const int roff = ((w >> 2) << 7) + (lane << 2);   // row offset in [0,256)
    const int c0 = (w & 3) << 4;                      // col group base
    ull acc[2][16];
#pragma unroll
    for (int c = 0; c < 16; c++) { acc[0][c] = 0ULL; acc[1][c] = 0ULL; }
    gemm64(Hs, Wd, acc, roff, c0);
    store_t(Got, acc, rbase, roff, c0);
}

// ---- Stage A: Vt = (relu(x@W_in + b_in) @ W_xh + b_h)^T --------------------
__global__ __launch_bounds__(256, 2)
void stageA_kernel(const float* __restrict__ x, const float* __restrict__ Win,
                   const float* __restrict__ bin, const float* __restrict__ Wxh,
                   const float* __restrict__ bh, float* __restrict__ Vt) {
    extern __shared__ float sm[];
    float* Us  = sm;                // [64][256]
    float* Wd  = sm + 16384;        // [64][128] dup W_xh
    float* Wi  = Wd + 8192;         // [16][64] W_in
    float* bi  = Wi + 1024;         // [64]
    float* bhd = bi + 64;           // [128] dup b_h
    const int tid = threadIdx.x;
    const size_t rbase = (size_t)blockIdx.x * 256;

#pragma unroll
    for (int i = tid; i < 4096; i += 256) {
        const float w = Wxh[i];
        Wd[2 * i] = w; Wd[2 * i + 1] = w;
    }
#pragma unroll
    for (int i = tid; i < 1024; i += 256) Wi[i] = Win[i];
    if (tid < 64) {
        bi[tid] = bin[tid];
        const float b = bh[tid];
        bhd[2 * tid] = b; bhd[2 * tid + 1] = b;
    }
    __syncthreads();

    {   // A1: u = relu(x@W_in + b_in), one thread per row, all 64 cols
        const size_t row = rbase + tid;
        float xr[16];
        const float4* xp = (const float4*)(x + row * NX);
#pragma unroll
        for (int q = 0; q < 4; q++) {
            const float4 t = xp[q];
            xr[q * 4] = t.x; xr[q * 4 + 1] = t.y; xr[q * 4 + 2] = t.z; xr[q * 4 + 3] = t.w;
        }
        ull ua[32];
        const ull* bp = (const ull*)bi;
#pragma unroll
        for (int j = 0; j < 32; j++) ua[j] = bp[j];
#pragma unroll
        for (int k = 0; k < 16; k++) {
            const ull xs = pk2(xr[k], xr[k]);
            const ulonglong2* wp = (const ulonglong2*)(Wi + (k << 6));
#pragma unroll
            for (int j = 0; j < 16; j++) {
                const ulonglong2 w = wp[j];
                ua[2 * j]     = fma2(xs, w.x, ua[2 * j]);
                ua[2 * j + 1] = fma2(xs, w.y, ua[2 * j + 1]);
            }
        }
#pragma unroll
        for (int j = 0; j < 32; j++) {
            const float2 f = up2(ua[j]);
            Us[(2 * j) * 256 + tid]     = fmaxf(f.x, 0.0f);
            Us[(2 * j + 1) * 256 + tid] = fmaxf(f.y, 0.0f);
        }
    }
    __syncthreads();

    // A2: V = u @ W_xh + b_h
    const int w = tid >> 5, lane = tid & 31;
    const int roff = ((w >> 2) << 7) + (lane << 2);
    const int c0 = (w & 3) << 4;
    ull acc[2][16];
#pragma unroll
    for (int c = 0; c < 16; c++) {
        const ull b = *(const ull*)(bhd + ((c0 + c) << 1));
        acc[0][c] = b; acc[1][c] = b;
    }
    gemm64(Us, Wd, acc, roff, c0);
    store_t(Vt, acc, rbase, roff, c0);
}

// ---- Stage E: out[t] = tanh(V[t-1] + G3[t-2]) @ W_out + b_out --------------
__global__ __launch_bounds__(256)
void stageE_kernel(const float* __restrict__ Vt, const float* __restrict__ Gt,
                   const float* __restrict__ Wout, const float* __restrict__ bout,
                   float* __restrict__ out) {
    __shared__ float wo[64];
    if (threadIdx.x < 64) wo[threadIdx.x] = Wout[threadIdx.x];
    __syncthreads();
    const size_t row = (size_t)blockIdx.x * 256 + threadIdx.x + (size_t)3 * NGRID;
    const float* vp = Vt + row;
    const float* gp = Gt + row - NGRID;
    float y = bout[0];
#pragma unroll 16
    for (int k = 0; k < 64; k++)
        y += ftanh(vp[(size_t)k * NROWS] + gp[(size_t)k * NROWS]) * wo[k];
    out[row + NGRID] = y;
}

__global__ void zero_head(float* __restrict__ out) {
    out[(size_t)blockIdx.x * 1024 + threadIdx.x] = 0.0f;   // t in [0,4)
}

// ---------------------------------------------------------------------------
extern "C" void kernel_launch(void* const* d_in, const int* in_sizes, int n_in,
                              void* d_out, int out_size) {
    const float* x    = (const float*)d_in[0];
    const float* Win  = (const float*)d_in[1];
    const float* bin  = (const float*)d_in[2];
    const float* Wxh  = (const float*)d_in[3];
    const float* Whh  = (const float*)d_in[4];
    const float* bh   = (const float*)d_in[5];
    const float* Wout = (const float*)d_in[6];
    const float* bout = (const float*)d_in[7];
    float* out = (float*)d_out;

    float *V, *Ga, *Gb;
    cudaGetSymbolAddress((void**)&V,  g_V);
    cudaGetSymbolAddress((void**)&Ga, g_Ga);
    cudaGetSymbolAddress((void**)&Gb, g_Gb);

    cudaFuncSetAttribute(stageA_kernel, cudaFuncAttributeMaxDynamicSharedMemorySize, SMEM_A);
    cudaFuncSetAttribute(step_kernel<false>, cudaFuncAttributeMaxDynamicSharedMemorySize, SMEM_STEP);
    cudaFuncSetAttribute(step_kernel<true>,  cudaFuncAttributeMaxDynamicSharedMemorySize, SMEM_STEP);

    const int NB = NROWS / 256;   // 4096 blocks

    zero_head<<<8, 1024>>>(out);
    stageA_kernel<<<NB, 256, SMEM_A>>>(x, Win, bin, Wxh, bh, V);
    step_kernel<false><<<NB, 256, SMEM_STEP>>>(V, V,  Whh, Ga);   // G1
    step_kernel<true ><<<NB, 256, SMEM_STEP>>>(V, Ga, Whh, Gb);   // G2
    step_kernel<true ><<<NB, 256, SMEM_STEP>>>(V, Gb, Whh, Ga);   // G3
    stageE_kernel<<<(508 * NGRID) / 256, 256>>>(V, Ga, Wout, bout, out);
}